// round 5
// baseline (speedup 1.0000x reference)
#include <cuda_runtime.h>
#include <cuda_fp16.h>

// LightGCN: out = (x + A@x + A@A@x + A@A@A@x) / 4, COO -> per-call CSR build,
// then warp-per-row gather SpMM (fp16 intermediates), layer 3 fused with mean.
// R5: convert fused into hist kernel, 4-edge-vectorized hist/scatter,
// cursor-atomic scatter (one random access per edge), cursor init in scan.

#define D      128
#define DV     32        // float4 per row
#define MAX_N  100032
#define MAX_E  3200000
#define SCAN_B 256

struct __align__(8) Edge { int c; float v; };

__device__ int    g_count[MAX_N];
__device__ int    g_cursor[MAX_N];
__device__ int    g_rowptr[MAX_N + 1];
__device__ int    g_blocksum[(MAX_N + SCAN_B - 1) / SCAN_B + 1];
__device__ Edge   g_edges[MAX_E];
__device__ __half g_xh [(size_t)MAX_N * D];
__device__ __half g_b1h[(size_t)MAX_N * D];
__device__ __half g_b2h[(size_t)MAX_N * D];

// ------------------------------------------------- fused convert + histogram

// Threads [0, n4): convert one float4 of x to fp16.
// Threads [0, E/4): additionally histogram 4 edges (int4 coalesced).
__global__ void convert_hist_kernel(const float4* __restrict__ x,
                                    uint2* __restrict__ xh, int n4,
                                    const int4* __restrict__ rows4, int e4,
                                    const int* __restrict__ rows, int E) {
    int i = blockIdx.x * blockDim.x + threadIdx.x;
    if (i < n4) {
        float4 v = x[i];
        uint2 o;
        *reinterpret_cast<__half2*>(&o.x) = __floats2half2_rn(v.x, v.y);
        *reinterpret_cast<__half2*>(&o.y) = __floats2half2_rn(v.z, v.w);
        xh[i] = o;
    }
    if (i < e4) {
        int4 r = rows4[i];
        atomicAdd(&g_count[r.x], 1);
        atomicAdd(&g_count[r.y], 1);
        atomicAdd(&g_count[r.z], 1);
        atomicAdd(&g_count[r.w], 1);
    } else {
        // scalar tail (E not divisible by 4)
        int t = e4 * 4 + (i - e4);
        if (i >= e4 && t < E && (i - e4) < 4) atomicAdd(&g_count[rows[t]], 1);
    }
}

// ---------------------------------------------------------------- scan (3 phase)

__global__ void scan_reduce_kernel(int n) {
    __shared__ int s[SCAN_B];
    int i = blockIdx.x * SCAN_B + threadIdx.x;
    s[threadIdx.x] = (i < n) ? g_count[i] : 0;
    __syncthreads();
    for (int off = SCAN_B / 2; off > 0; off >>= 1) {
        if (threadIdx.x < off) s[threadIdx.x] += s[threadIdx.x + off];
        __syncthreads();
    }
    if (threadIdx.x == 0) g_blocksum[blockIdx.x] = s[0];
}

__global__ void scan_partials_kernel(int nblocks) {
    __shared__ int s[512];
    int tid = threadIdx.x;
    int v = (tid < nblocks) ? g_blocksum[tid] : 0;
    s[tid] = v;
    __syncthreads();
    for (int off = 1; off < 512; off <<= 1) {
        int t = (tid >= off) ? s[tid - off] : 0;
        __syncthreads();
        s[tid] += t;
        __syncthreads();
    }
    if (tid < nblocks) g_blocksum[tid] = s[tid] - v;   // exclusive
}

// Per-block exclusive rescan + offset; also initializes the scatter cursor.
__global__ void scan_final_kernel(int n, int E) {
    __shared__ int s[SCAN_B];
    int i = blockIdx.x * SCAN_B + threadIdx.x;
    int v = (i < n) ? g_count[i] : 0;
    s[threadIdx.x] = v;
    __syncthreads();
    for (int off = 1; off < SCAN_B; off <<= 1) {
        int t = (threadIdx.x >= off) ? s[threadIdx.x - off] : 0;
        __syncthreads();
        s[threadIdx.x] += t;
        __syncthreads();
    }
    if (i < n) {
        int rp = g_blocksum[blockIdx.x] + s[threadIdx.x] - v;
        g_rowptr[i] = rp;
        g_cursor[i] = rp;
    }
    if (i == n - 1 || (i == n && threadIdx.x == 0)) g_rowptr[n] = E;
}

// ---------------------------------------------------------------- scatter

// 4 edges per thread: coalesced int4/float4 reads, 4 independent
// random atomic+store chains in flight.
__global__ void scatter_kernel(const int4* __restrict__ rows4,
                               const int4* __restrict__ cols4,
                               const float4* __restrict__ vals4, int e4,
                               const int* __restrict__ rows,
                               const int* __restrict__ cols,
                               const float* __restrict__ vals, int E) {
    int i = blockIdx.x * blockDim.x + threadIdx.x;
    if (i < e4) {
        int4 r = rows4[i];
        int4 c = cols4[i];
        float4 v = vals4[i];
        int p0 = atomicAdd(&g_cursor[r.x], 1);
        int p1 = atomicAdd(&g_cursor[r.y], 1);
        int p2 = atomicAdd(&g_cursor[r.z], 1);
        int p3 = atomicAdd(&g_cursor[r.w], 1);
        Edge e0; e0.c = c.x; e0.v = v.x; g_edges[p0] = e0;
        Edge e1; e1.c = c.y; e1.v = v.y; g_edges[p1] = e1;
        Edge e2; e2.c = c.z; e2.v = v.z; g_edges[p2] = e2;
        Edge e3; e3.c = c.w; e3.v = v.w; g_edges[p3] = e3;
    } else {
        int t = e4 * 4 + (i - e4);
        if (t < E && (i - e4) < 4) {
            int p = atomicAdd(&g_cursor[rows[t]], 1);
            Edge e; e.c = cols[t]; e.v = vals[t];
            g_edges[p] = e;
        }
    }
}

// ---------------------------------------------------------------- SpMM (half)

__device__ __forceinline__ void gather_fma(float4& acc, float v, uint2 t) {
    float2 lo = __half22float2(*reinterpret_cast<const __half2*>(&t.x));
    float2 hi = __half22float2(*reinterpret_cast<const __half2*>(&t.y));
    acc.x += v * lo.x;
    acc.y += v * lo.y;
    acc.z += v * hi.x;
    acc.w += v * hi.y;
}

// One warp per output row; lane owns dims [4*lane, 4*lane+4). 4x unrolled.
__device__ __forceinline__ float4 spmm_row(const uint2* __restrict__ src,
                                           int w, int lane) {
    int beg = g_rowptr[w];
    int end = g_rowptr[w + 1];
    float4 acc = make_float4(0.f, 0.f, 0.f, 0.f);
    int i = beg;
    for (; i + 4 <= end; i += 4) {
        Edge e0 = g_edges[i];
        Edge e1 = g_edges[i + 1];
        Edge e2 = g_edges[i + 2];
        Edge e3 = g_edges[i + 3];
        uint2 t0 = __ldg(src + (size_t)e0.c * DV + lane);
        uint2 t1 = __ldg(src + (size_t)e1.c * DV + lane);
        uint2 t2 = __ldg(src + (size_t)e2.c * DV + lane);
        uint2 t3 = __ldg(src + (size_t)e3.c * DV + lane);
        gather_fma(acc, e0.v, t0);
        gather_fma(acc, e1.v, t1);
        gather_fma(acc, e2.v, t2);
        gather_fma(acc, e3.v, t3);
    }
    for (; i < end; ++i) {
        Edge e = g_edges[i];
        uint2 t = __ldg(src + (size_t)e.c * DV + lane);
        gather_fma(acc, e.v, t);
    }
    return acc;
}

__global__ void spmm_h_kernel(const uint2* __restrict__ src,
                              uint2* __restrict__ dst, int n) {
    int w = (blockIdx.x * blockDim.x + threadIdx.x) >> 5;
    int lane = threadIdx.x & 31;
    if (w >= n) return;
    float4 acc = spmm_row(src, w, lane);
    uint2 o;
    *reinterpret_cast<__half2*>(&o.x) = __floats2half2_rn(acc.x, acc.y);
    *reinterpret_cast<__half2*>(&o.y) = __floats2half2_rn(acc.z, acc.w);
    dst[(size_t)w * DV + lane] = o;
}

// Layer 3 fused with the mean: out = 0.25 * (x + b1 + b2 + A@b2)
__global__ void spmm_final_kernel(const uint2* __restrict__ b2,
                                  const float4* __restrict__ x,
                                  const uint2* __restrict__ b1,
                                  float4* __restrict__ out, int n) {
    int w = (blockIdx.x * blockDim.x + threadIdx.x) >> 5;
    int lane = threadIdx.x & 31;
    if (w >= n) return;
    float4 acc = spmm_row(b2, w, lane);

    size_t idx = (size_t)w * DV + lane;
    float4 xv = x[idx];
    uint2 u1 = b1[idx];
    uint2 u2 = b2[idx];
    float2 a = __half22float2(*reinterpret_cast<const __half2*>(&u1.x));
    float2 b = __half22float2(*reinterpret_cast<const __half2*>(&u1.y));
    float2 c = __half22float2(*reinterpret_cast<const __half2*>(&u2.x));
    float2 d = __half22float2(*reinterpret_cast<const __half2*>(&u2.y));

    float4 o;
    o.x = 0.25f * (xv.x + a.x + c.x + acc.x);
    o.y = 0.25f * (xv.y + a.y + c.y + acc.y);
    o.z = 0.25f * (xv.z + b.x + d.x + acc.z);
    o.w = 0.25f * (xv.w + b.y + d.y + acc.w);
    out[idx] = o;
}

// ---------------------------------------------------------------- launch

extern "C" void kernel_launch(void* const* d_in, const int* in_sizes, int n_in,
                              void* d_out, int out_size) {
    const float* x  = (const float*)d_in[0];
    const int*   er = (const int*)d_in[1];
    const int*   ec = (const int*)d_in[2];
    const float* ev = (const float*)d_in[3];

    int E = in_sizes[1];
    int N = in_sizes[0] / D;

    void *xhp, *b1p, *b2p, *cntp;
    cudaGetSymbolAddress(&xhp, g_xh);
    cudaGetSymbolAddress(&b1p, g_b1h);
    cudaGetSymbolAddress(&b2p, g_b2h);
    cudaGetSymbolAddress(&cntp, g_count);

    const int TPB = 256;
    int n4 = N * DV;                       // float4 count of x
    int e4 = E / 4;                        // vectorized edge quads
    int nsb = (N + SCAN_B - 1) / SCAN_B;   // scan blocks (<=512)

    cudaMemsetAsync(cntp, 0, (size_t)N * sizeof(int));

    // fused fp16 convert + edge histogram
    int ch_threads = (n4 > e4 + 4) ? n4 : (e4 + 4);
    convert_hist_kernel<<<(ch_threads + TPB - 1) / TPB, TPB>>>(
        (const float4*)x, (uint2*)xhp, n4,
        (const int4*)er, e4, er, E);

    scan_reduce_kernel<<<nsb, SCAN_B>>>(N);
    scan_partials_kernel<<<1, 512>>>(nsb);
    scan_final_kernel<<<nsb, SCAN_B>>>(N, E);

    scatter_kernel<<<(e4 + 4 + TPB - 1) / TPB, TPB>>>(
        (const int4*)er, (const int4*)ec, (const float4*)ev, e4,
        er, ec, ev, E);

    // 3 propagation layers (layer 3 fused with final mean)
    int spmm_blocks = (N * 32 + TPB - 1) / TPB;
    spmm_h_kernel<<<spmm_blocks, TPB>>>((const uint2*)xhp, (uint2*)b1p, N);
    spmm_h_kernel<<<spmm_blocks, TPB>>>((const uint2*)b1p, (uint2*)b2p, N);
    spmm_final_kernel<<<spmm_blocks, TPB>>>((const uint2*)b2p,
                                            (const float4*)x,
                                            (const uint2*)b1p,
                                            (float4*)d_out, N);
}

// round 6
// speedup vs baseline: 1.1132x; 1.1132x over previous
#include <cuda_runtime.h>
#include <cuda_fp16.h>

// LightGCN: out = (x + A@x + A@A@x + A@A@A@x) / 4, COO -> per-call CSR build,
// then warp-per-row gather SpMM (fp16 intermediates), layer 3 fused with mean.
// R6: revert to R4 scatter scheme (offs captured in hist, atomic-free scatter);
// single-kernel decoupled-lookback scan; convert overlapped with hist via
// block-role split.

#define D        128
#define DV       32          // float4 per row
#define MAX_N    100352      // padded to scan-tile multiple; tail stays 0
#define MAX_E    3200000
#define SCAN_TILE 1024       // 256 threads * 4 items
#define MAX_TILES ((MAX_N + SCAN_TILE - 1) / SCAN_TILE)

struct __align__(8) Edge { int c; float v; };

__device__ int    g_count[MAX_N];                    // static zero; memset N/call
__device__ int    g_offs[MAX_E];
__device__ int    g_rowptr[MAX_N + 1];
__device__ unsigned long long g_tile_state[MAX_TILES];
__device__ Edge   g_edges[MAX_E];
__device__ __half g_xh [(size_t)MAX_N * D];
__device__ __half g_b1h[(size_t)MAX_N * D];
__device__ __half g_b2h[(size_t)MAX_N * D];

// ----------------------------------------- fused convert (blocks [0,CB)) + hist

__global__ void hist_convert_kernel(const float4* __restrict__ x,
                                    uint2* __restrict__ xh, int n4,
                                    const int* __restrict__ rows, int E,
                                    int conv_blocks) {
    if (blockIdx.x < conv_blocks) {
        int stride = conv_blocks * blockDim.x;
        for (int i = blockIdx.x * blockDim.x + threadIdx.x; i < n4; i += stride) {
            float4 v = x[i];
            uint2 o;
            *reinterpret_cast<__half2*>(&o.x) = __floats2half2_rn(v.x, v.y);
            *reinterpret_cast<__half2*>(&o.y) = __floats2half2_rn(v.z, v.w);
            xh[i] = o;
        }
    } else {
        int i = (blockIdx.x - conv_blocks) * blockDim.x + threadIdx.x;
        if (i < E) g_offs[i] = atomicAdd(&g_count[rows[i]], 1);
    }
}

// --------------------------------------- single-pass scan (decoupled lookback)

// Tile state: bits[32+] = status (0 invalid, 1 aggregate, 2 inclusive),
// bits[31:0] = value. One 64-bit store publishes both atomically.
__global__ void scan_kernel(int n, int E) {
    __shared__ int s_warp[8];
    __shared__ int s_prefix;
    int tile = blockIdx.x;
    int t = threadIdx.x;
    int lane = t & 31, wid = t >> 5;
    int base = tile * SCAN_TILE + t * 4;

    // padded region of g_count is permanently zero -> unguarded int4 load OK
    int4 c = *reinterpret_cast<const int4*>(&g_count[base]);
    int sum = c.x + c.y + c.z + c.w;

    // warp inclusive scan of per-thread sums
    int v = sum;
    #pragma unroll
    for (int off = 1; off < 32; off <<= 1) {
        int tv = __shfl_up_sync(0xffffffffu, v, off);
        if (lane >= off) v += tv;
    }
    if (lane == 31) s_warp[wid] = v;
    __syncthreads();
    if (wid == 0) {
        int wv = (lane < 8) ? s_warp[lane] : 0;
        #pragma unroll
        for (int off = 1; off < 8; off <<= 1) {
            int tv = __shfl_up_sync(0xffffffffu, wv, off);
            if (lane >= off) wv += tv;
        }
        if (lane < 8) s_warp[lane] = wv;
    }
    __syncthreads();
    int block_total = s_warp[7];
    int thr_excl = ((wid ? s_warp[wid - 1] : 0)) + v - sum;

    // publish aggregate (tile 0 publishes inclusive directly)
    if (t == 0) {
        unsigned long long st = (tile == 0)
            ? ((2ULL << 32) | (unsigned int)block_total)
            : ((1ULL << 32) | (unsigned int)block_total);
        atomicExch(&g_tile_state[tile], st);
        if (tile == 0) s_prefix = 0;
    }

    // warp 0 performs warp-parallel lookback
    if (tile > 0 && wid == 0) {
        int prefix = 0;
        int windowEnd = tile;                  // window covers [windowEnd-32, windowEnd)
        for (;;) {
            int idx = windowEnd - 1 - lane;
            unsigned long long st;
            if (idx >= 0) {
                do { st = atomicAdd(&g_tile_state[idx], 0ULL); }
                while ((st >> 32) == 0ULL);
            } else {
                st = (2ULL << 32);             // virtual inclusive 0
            }
            unsigned status = (unsigned)(st >> 32);
            int val = (int)(unsigned)st;
            unsigned ballot = __ballot_sync(0xffffffffu, status == 2u);
            int firstIncl = __ffs(ballot) - 1;       // closest inclusive (lowest lane)
            int contrib;
            if (ballot) contrib = (lane <= firstIncl) ? val : 0;
            else        contrib = val;               // all aggregates: take all, slide
            #pragma unroll
            for (int off = 16; off > 0; off >>= 1)
                contrib += __shfl_down_sync(0xffffffffu, contrib, off);
            contrib = __shfl_sync(0xffffffffu, contrib, 0);
            prefix += contrib;
            if (ballot) break;
            windowEnd -= 32;
        }
        if (lane == 0) {
            s_prefix = prefix;
            atomicExch(&g_tile_state[tile],
                       (2ULL << 32) | (unsigned int)(prefix + block_total));
        }
    }
    __syncthreads();
    int prefix = s_prefix;

    // exclusive rowptr; index n (count 0) lands rowptr[n] = E automatically
    int p0 = prefix + thr_excl;
    int4 o;
    o.x = p0;
    o.y = p0 + c.x;
    o.z = p0 + c.x + c.y;
    o.w = p0 + c.x + c.y + c.z;
    if (base + 3 <= n) {
        *reinterpret_cast<int4*>(&g_rowptr[base]) = o;
    } else {
        if (base     <= n) g_rowptr[base]     = o.x;
        if (base + 1 <= n) g_rowptr[base + 1] = o.y;
        if (base + 2 <= n) g_rowptr[base + 2] = o.z;
        if (base + 3 <= n) g_rowptr[base + 3] = o.w;
    }
}

// ---------------------------------------------------------------- scatter

// Atomic-free: slot = rowptr[row] + precomputed within-row offset.
__global__ void scatter_kernel(const int* __restrict__ rows,
                               const int* __restrict__ cols,
                               const float* __restrict__ vals, int E) {
    int i = blockIdx.x * blockDim.x + threadIdx.x;
    if (i < E) {
        int pos = g_rowptr[rows[i]] + g_offs[i];
        Edge e;
        e.c = cols[i];
        e.v = vals[i];
        g_edges[pos] = e;
    }
}

// ---------------------------------------------------------------- SpMM (half)

__device__ __forceinline__ void gather_fma(float4& acc, float v, uint2 t) {
    float2 lo = __half22float2(*reinterpret_cast<const __half2*>(&t.x));
    float2 hi = __half22float2(*reinterpret_cast<const __half2*>(&t.y));
    acc.x += v * lo.x;
    acc.y += v * lo.y;
    acc.z += v * hi.x;
    acc.w += v * hi.y;
}

// One warp per output row; lane owns dims [4*lane, 4*lane+4). 4x unrolled.
__device__ __forceinline__ float4 spmm_row(const uint2* __restrict__ src,
                                           int w, int lane) {
    int beg = g_rowptr[w];
    int end = g_rowptr[w + 1];
    float4 acc = make_float4(0.f, 0.f, 0.f, 0.f);
    int i = beg;
    for (; i + 4 <= end; i += 4) {
        Edge e0 = g_edges[i];
        Edge e1 = g_edges[i + 1];
        Edge e2 = g_edges[i + 2];
        Edge e3 = g_edges[i + 3];
        uint2 t0 = __ldg(src + (size_t)e0.c * DV + lane);
        uint2 t1 = __ldg(src + (size_t)e1.c * DV + lane);
        uint2 t2 = __ldg(src + (size_t)e2.c * DV + lane);
        uint2 t3 = __ldg(src + (size_t)e3.c * DV + lane);
        gather_fma(acc, e0.v, t0);
        gather_fma(acc, e1.v, t1);
        gather_fma(acc, e2.v, t2);
        gather_fma(acc, e3.v, t3);
    }
    for (; i < end; ++i) {
        Edge e = g_edges[i];
        uint2 t = __ldg(src + (size_t)e.c * DV + lane);
        gather_fma(acc, e.v, t);
    }
    return acc;
}

__global__ void spmm_h_kernel(const uint2* __restrict__ src,
                              uint2* __restrict__ dst, int n) {
    int w = (blockIdx.x * blockDim.x + threadIdx.x) >> 5;
    int lane = threadIdx.x & 31;
    if (w >= n) return;
    float4 acc = spmm_row(src, w, lane);
    uint2 o;
    *reinterpret_cast<__half2*>(&o.x) = __floats2half2_rn(acc.x, acc.y);
    *reinterpret_cast<__half2*>(&o.y) = __floats2half2_rn(acc.z, acc.w);
    dst[(size_t)w * DV + lane] = o;
}

// Layer 3 fused with the mean: out = 0.25 * (x + b1 + b2 + A@b2)
__global__ void spmm_final_kernel(const uint2* __restrict__ b2,
                                  const float4* __restrict__ x,
                                  const uint2* __restrict__ b1,
                                  float4* __restrict__ out, int n) {
    int w = (blockIdx.x * blockDim.x + threadIdx.x) >> 5;
    int lane = threadIdx.x & 31;
    if (w >= n) return;
    float4 acc = spmm_row(b2, w, lane);

    size_t idx = (size_t)w * DV + lane;
    float4 xv = x[idx];
    uint2 u1 = b1[idx];
    uint2 u2 = b2[idx];
    float2 a = __half22float2(*reinterpret_cast<const __half2*>(&u1.x));
    float2 b = __half22float2(*reinterpret_cast<const __half2*>(&u1.y));
    float2 c = __half22float2(*reinterpret_cast<const __half2*>(&u2.x));
    float2 d = __half22float2(*reinterpret_cast<const __half2*>(&u2.y));

    float4 o;
    o.x = 0.25f * (xv.x + a.x + c.x + acc.x);
    o.y = 0.25f * (xv.y + a.y + c.y + acc.y);
    o.z = 0.25f * (xv.z + b.x + d.x + acc.z);
    o.w = 0.25f * (xv.w + b.y + d.y + acc.w);
    out[idx] = o;
}

// ---------------------------------------------------------------- launch

extern "C" void kernel_launch(void* const* d_in, const int* in_sizes, int n_in,
                              void* d_out, int out_size) {
    const float* x  = (const float*)d_in[0];
    const int*   er = (const int*)d_in[1];
    const int*   ec = (const int*)d_in[2];
    const float* ev = (const float*)d_in[3];

    int E = in_sizes[1];
    int N = in_sizes[0] / D;

    void *xhp, *b1p, *b2p, *cntp, *tsp;
    cudaGetSymbolAddress(&xhp, g_xh);
    cudaGetSymbolAddress(&b1p, g_b1h);
    cudaGetSymbolAddress(&b2p, g_b2h);
    cudaGetSymbolAddress(&cntp, g_count);
    cudaGetSymbolAddress(&tsp, g_tile_state);

    const int TPB = 256;
    int n4 = N * DV;                                  // float4 count of x
    int ntiles = (N + SCAN_TILE) / SCAN_TILE;         // covers index N too

    cudaMemsetAsync(cntp, 0, (size_t)N * sizeof(int));
    cudaMemsetAsync(tsp, 0, (size_t)ntiles * sizeof(unsigned long long));

    // convert (first conv_blocks, grid-stride) runs concurrently with hist
    const int conv_blocks = 1024;
    int edge_blocks = (E + TPB - 1) / TPB;
    hist_convert_kernel<<<conv_blocks + edge_blocks, TPB>>>(
        (const float4*)x, (uint2*)xhp, n4, er, E, conv_blocks);

    scan_kernel<<<ntiles, TPB>>>(N, E);

    scatter_kernel<<<edge_blocks, TPB>>>(er, ec, ev, E);

    // 3 propagation layers (layer 3 fused with final mean)
    int spmm_blocks = (N * 32 + TPB - 1) / TPB;
    spmm_h_kernel<<<spmm_blocks, TPB>>>((const uint2*)xhp, (uint2*)b1p, N);
    spmm_h_kernel<<<spmm_blocks, TPB>>>((const uint2*)b1p, (uint2*)b2p, N);
    spmm_final_kernel<<<spmm_blocks, TPB>>>((const uint2*)b2p,
                                            (const float4*)x,
                                            (const uint2*)b1p,
                                            (float4*)d_out, N);
}

// round 7
// speedup vs baseline: 1.1802x; 1.0602x over previous
#include <cuda_runtime.h>
#include <cuda_fp16.h>

// LightGCN: out = (x + A@x + A@A@x + A@A@A@x) / 4, COO -> per-call CSR build,
// then warp-per-row gather SpMM (fp16 intermediates), layer 3 fused with mean.
// R7: SpMM inner loop unrolled to 8 edges with uint4 edge pair-loads
// (latency-bound per R6 ncu: issue=49%, L2=42%, nothing saturated).

#define D        128
#define DV       32          // float4 per row
#define MAX_N    100352      // padded to scan-tile multiple; tail stays 0
#define MAX_E    3200000
#define SCAN_TILE 1024       // 256 threads * 4 items
#define MAX_TILES ((MAX_N + SCAN_TILE - 1) / SCAN_TILE)

struct __align__(8) Edge { int c; float v; };

__device__ int    g_count[MAX_N];                    // static zero; memset N/call
__device__ int    g_offs[MAX_E];
__device__ int    g_rowptr[MAX_N + 1];
__device__ unsigned long long g_tile_state[MAX_TILES];
__device__ __align__(16) Edge g_edges[MAX_E];
__device__ __half g_xh [(size_t)MAX_N * D];
__device__ __half g_b1h[(size_t)MAX_N * D];
__device__ __half g_b2h[(size_t)MAX_N * D];

// ----------------------------------------- fused convert (blocks [0,CB)) + hist

__global__ void hist_convert_kernel(const float4* __restrict__ x,
                                    uint2* __restrict__ xh, int n4,
                                    const int* __restrict__ rows, int E,
                                    int conv_blocks) {
    if (blockIdx.x < conv_blocks) {
        int stride = conv_blocks * blockDim.x;
        for (int i = blockIdx.x * blockDim.x + threadIdx.x; i < n4; i += stride) {
            float4 v = x[i];
            uint2 o;
            *reinterpret_cast<__half2*>(&o.x) = __floats2half2_rn(v.x, v.y);
            *reinterpret_cast<__half2*>(&o.y) = __floats2half2_rn(v.z, v.w);
            xh[i] = o;
        }
    } else {
        int i = (blockIdx.x - conv_blocks) * blockDim.x + threadIdx.x;
        if (i < E) g_offs[i] = atomicAdd(&g_count[rows[i]], 1);
    }
}

// --------------------------------------- single-pass scan (decoupled lookback)

// Tile state: bits[32+] = status (0 invalid, 1 aggregate, 2 inclusive),
// bits[31:0] = value. One 64-bit store publishes both atomically.
__global__ void scan_kernel(int n, int E) {
    __shared__ int s_warp[8];
    __shared__ int s_prefix;
    int tile = blockIdx.x;
    int t = threadIdx.x;
    int lane = t & 31, wid = t >> 5;
    int base = tile * SCAN_TILE + t * 4;

    // padded region of g_count is permanently zero -> unguarded int4 load OK
    int4 c = *reinterpret_cast<const int4*>(&g_count[base]);
    int sum = c.x + c.y + c.z + c.w;

    // warp inclusive scan of per-thread sums
    int v = sum;
    #pragma unroll
    for (int off = 1; off < 32; off <<= 1) {
        int tv = __shfl_up_sync(0xffffffffu, v, off);
        if (lane >= off) v += tv;
    }
    if (lane == 31) s_warp[wid] = v;
    __syncthreads();
    if (wid == 0) {
        int wv = (lane < 8) ? s_warp[lane] : 0;
        #pragma unroll
        for (int off = 1; off < 8; off <<= 1) {
            int tv = __shfl_up_sync(0xffffffffu, wv, off);
            if (lane >= off) wv += tv;
        }
        if (lane < 8) s_warp[lane] = wv;
    }
    __syncthreads();
    int block_total = s_warp[7];
    int thr_excl = ((wid ? s_warp[wid - 1] : 0)) + v - sum;

    // publish aggregate (tile 0 publishes inclusive directly)
    if (t == 0) {
        unsigned long long st = (tile == 0)
            ? ((2ULL << 32) | (unsigned int)block_total)
            : ((1ULL << 32) | (unsigned int)block_total);
        atomicExch(&g_tile_state[tile], st);
        if (tile == 0) s_prefix = 0;
    }

    // warp 0 performs warp-parallel lookback
    if (tile > 0 && wid == 0) {
        int prefix = 0;
        int windowEnd = tile;                  // window covers [windowEnd-32, windowEnd)
        for (;;) {
            int idx = windowEnd - 1 - lane;
            unsigned long long st;
            if (idx >= 0) {
                do { st = atomicAdd(&g_tile_state[idx], 0ULL); }
                while ((st >> 32) == 0ULL);
            } else {
                st = (2ULL << 32);             // virtual inclusive 0
            }
            unsigned status = (unsigned)(st >> 32);
            int val = (int)(unsigned)st;
            unsigned ballot = __ballot_sync(0xffffffffu, status == 2u);
            int firstIncl = __ffs(ballot) - 1;       // closest inclusive (lowest lane)
            int contrib;
            if (ballot) contrib = (lane <= firstIncl) ? val : 0;
            else        contrib = val;               // all aggregates: take all, slide
            #pragma unroll
            for (int off = 16; off > 0; off >>= 1)
                contrib += __shfl_down_sync(0xffffffffu, contrib, off);
            contrib = __shfl_sync(0xffffffffu, contrib, 0);
            prefix += contrib;
            if (ballot) break;
            windowEnd -= 32;
        }
        if (lane == 0) {
            s_prefix = prefix;
            atomicExch(&g_tile_state[tile],
                       (2ULL << 32) | (unsigned int)(prefix + block_total));
        }
    }
    __syncthreads();
    int prefix = s_prefix;

    // exclusive rowptr; index n (count 0) lands rowptr[n] = E automatically
    int p0 = prefix + thr_excl;
    int4 o;
    o.x = p0;
    o.y = p0 + c.x;
    o.z = p0 + c.x + c.y;
    o.w = p0 + c.x + c.y + c.z;
    if (base + 3 <= n) {
        *reinterpret_cast<int4*>(&g_rowptr[base]) = o;
    } else {
        if (base     <= n) g_rowptr[base]     = o.x;
        if (base + 1 <= n) g_rowptr[base + 1] = o.y;
        if (base + 2 <= n) g_rowptr[base + 2] = o.z;
        if (base + 3 <= n) g_rowptr[base + 3] = o.w;
    }
}

// ---------------------------------------------------------------- scatter

// Atomic-free: slot = rowptr[row] + precomputed within-row offset.
__global__ void scatter_kernel(const int* __restrict__ rows,
                               const int* __restrict__ cols,
                               const float* __restrict__ vals, int E) {
    int i = blockIdx.x * blockDim.x + threadIdx.x;
    if (i < E) {
        int pos = g_rowptr[rows[i]] + g_offs[i];
        Edge e;
        e.c = cols[i];
        e.v = vals[i];
        g_edges[pos] = e;
    }
}

// ---------------------------------------------------------------- SpMM (half)

__device__ __forceinline__ void gather_fma(float4& acc, float v, uint2 t) {
    float2 lo = __half22float2(*reinterpret_cast<const __half2*>(&t.x));
    float2 hi = __half22float2(*reinterpret_cast<const __half2*>(&t.y));
    acc.x += v * lo.x;
    acc.y += v * lo.y;
    acc.z += v * hi.x;
    acc.w += v * hi.y;
}

// One warp per output row; lane owns dims [4*lane, 4*lane+4).
// 8 edges in flight per iteration; edges pair-loaded as uint4 (LDG.128).
__device__ __forceinline__ float4 spmm_row(const uint2* __restrict__ src,
                                           int w, int lane) {
    int beg = g_rowptr[w];
    int end = g_rowptr[w + 1];
    float4 acc = make_float4(0.f, 0.f, 0.f, 0.f);
    int i = beg;

    // align to even index so uint4 pair-loads are 16B aligned
    if ((i & 1) && i < end) {
        Edge e = g_edges[i];
        uint2 t = __ldg(src + (size_t)e.c * DV + lane);
        gather_fma(acc, e.v, t);
        ++i;
    }

    for (; i + 8 <= end; i += 8) {
        uint4 p0 = *reinterpret_cast<const uint4*>(&g_edges[i]);
        uint4 p1 = *reinterpret_cast<const uint4*>(&g_edges[i + 2]);
        uint4 p2 = *reinterpret_cast<const uint4*>(&g_edges[i + 4]);
        uint4 p3 = *reinterpret_cast<const uint4*>(&g_edges[i + 6]);
        uint2 t0 = __ldg(src + (size_t)(int)p0.x * DV + lane);
        uint2 t1 = __ldg(src + (size_t)(int)p0.z * DV + lane);
        uint2 t2 = __ldg(src + (size_t)(int)p1.x * DV + lane);
        uint2 t3 = __ldg(src + (size_t)(int)p1.z * DV + lane);
        uint2 t4 = __ldg(src + (size_t)(int)p2.x * DV + lane);
        uint2 t5 = __ldg(src + (size_t)(int)p2.z * DV + lane);
        uint2 t6 = __ldg(src + (size_t)(int)p3.x * DV + lane);
        uint2 t7 = __ldg(src + (size_t)(int)p3.z * DV + lane);
        gather_fma(acc, __uint_as_float(p0.y), t0);
        gather_fma(acc, __uint_as_float(p0.w), t1);
        gather_fma(acc, __uint_as_float(p1.y), t2);
        gather_fma(acc, __uint_as_float(p1.w), t3);
        gather_fma(acc, __uint_as_float(p2.y), t4);
        gather_fma(acc, __uint_as_float(p2.w), t5);
        gather_fma(acc, __uint_as_float(p3.y), t6);
        gather_fma(acc, __uint_as_float(p3.w), t7);
    }

    for (; i + 2 <= end; i += 2) {
        uint4 p = *reinterpret_cast<const uint4*>(&g_edges[i]);
        uint2 t0 = __ldg(src + (size_t)(int)p.x * DV + lane);
        uint2 t1 = __ldg(src + (size_t)(int)p.z * DV + lane);
        gather_fma(acc, __uint_as_float(p.y), t0);
        gather_fma(acc, __uint_as_float(p.w), t1);
    }

    if (i < end) {
        Edge e = g_edges[i];
        uint2 t = __ldg(src + (size_t)e.c * DV + lane);
        gather_fma(acc, e.v, t);
    }
    return acc;
}

__global__ void __launch_bounds__(256, 5)
spmm_h_kernel(const uint2* __restrict__ src,
              uint2* __restrict__ dst, int n) {
    int w = (blockIdx.x * blockDim.x + threadIdx.x) >> 5;
    int lane = threadIdx.x & 31;
    if (w >= n) return;
    float4 acc = spmm_row(src, w, lane);
    uint2 o;
    *reinterpret_cast<__half2*>(&o.x) = __floats2half2_rn(acc.x, acc.y);
    *reinterpret_cast<__half2*>(&o.y) = __floats2half2_rn(acc.z, acc.w);
    dst[(size_t)w * DV + lane] = o;
}

// Layer 3 fused with the mean: out = 0.25 * (x + b1 + b2 + A@b2)
__global__ void __launch_bounds__(256, 5)
spmm_final_kernel(const uint2* __restrict__ b2,
                  const float4* __restrict__ x,
                  const uint2* __restrict__ b1,
                  float4* __restrict__ out, int n) {
    int w = (blockIdx.x * blockDim.x + threadIdx.x) >> 5;
    int lane = threadIdx.x & 31;
    if (w >= n) return;
    float4 acc = spmm_row(b2, w, lane);

    size_t idx = (size_t)w * DV + lane;
    float4 xv = x[idx];
    uint2 u1 = b1[idx];
    uint2 u2 = b2[idx];
    float2 a = __half22float2(*reinterpret_cast<const __half2*>(&u1.x));
    float2 b = __half22float2(*reinterpret_cast<const __half2*>(&u1.y));
    float2 c = __half22float2(*reinterpret_cast<const __half2*>(&u2.x));
    float2 d = __half22float2(*reinterpret_cast<const __half2*>(&u2.y));

    float4 o;
    o.x = 0.25f * (xv.x + a.x + c.x + acc.x);
    o.y = 0.25f * (xv.y + a.y + c.y + acc.y);
    o.z = 0.25f * (xv.z + b.x + d.x + acc.z);
    o.w = 0.25f * (xv.w + b.y + d.y + acc.w);
    out[idx] = o;
}

// ---------------------------------------------------------------- launch

extern "C" void kernel_launch(void* const* d_in, const int* in_sizes, int n_in,
                              void* d_out, int out_size) {
    const float* x  = (const float*)d_in[0];
    const int*   er = (const int*)d_in[1];
    const int*   ec = (const int*)d_in[2];
    const float* ev = (const float*)d_in[3];

    int E = in_sizes[1];
    int N = in_sizes[0] / D;

    void *xhp, *b1p, *b2p, *cntp, *tsp;
    cudaGetSymbolAddress(&xhp, g_xh);
    cudaGetSymbolAddress(&b1p, g_b1h);
    cudaGetSymbolAddress(&b2p, g_b2h);
    cudaGetSymbolAddress(&cntp, g_count);
    cudaGetSymbolAddress(&tsp, g_tile_state);

    const int TPB = 256;
    int n4 = N * DV;                                  // float4 count of x
    int ntiles = (N + SCAN_TILE) / SCAN_TILE;         // covers index N too

    cudaMemsetAsync(cntp, 0, (size_t)N * sizeof(int));
    cudaMemsetAsync(tsp, 0, (size_t)ntiles * sizeof(unsigned long long));

    // convert (first conv_blocks, grid-stride) runs concurrently with hist
    const int conv_blocks = 1024;
    int edge_blocks = (E + TPB - 1) / TPB;
    hist_convert_kernel<<<conv_blocks + edge_blocks, TPB>>>(
        (const float4*)x, (uint2*)xhp, n4, er, E, conv_blocks);

    scan_kernel<<<ntiles, TPB>>>(N, E);

    scatter_kernel<<<edge_blocks, TPB>>>(er, ec, ev, E);

    // 3 propagation layers (layer 3 fused with final mean)
    int spmm_blocks = (N * 32 + TPB - 1) / TPB;
    spmm_h_kernel<<<spmm_blocks, TPB>>>((const uint2*)xhp, (uint2*)b1p, N);
    spmm_h_kernel<<<spmm_blocks, TPB>>>((const uint2*)b1p, (uint2*)b2p, N);
    spmm_final_kernel<<<spmm_blocks, TPB>>>((const uint2*)b2p,
                                            (const float4*)x,
                                            (const uint2*)b1p,
                                            (float4*)d_out, N);
}